// round 11
// baseline (speedup 1.0000x reference)
#include <cuda_runtime.h>

#define DIMC 192
#define RJ   48          // DIM / RED
#define BB   4
#define HH   256
#define WW   256
#define HWSZ (HH * WW)   // 65536
#define EPSV 1e-5f
#define NPLANES (BB * DIMC)       // 768
#define ROWTILES (HH / 8)         // 32

// Scratch (no device allocation allowed).
__device__ float        g_pooled[NPLANES];
__device__ unsigned int g_sync = 0;   // monotonic ticket counter (replay-safe)

// ---------------------------------------------------------------------------
// One persistent kernel: pool -> grid barrier -> wgen (per-block) -> conv.
// 768 blocks x 256 threads; launch_bounds(256,6) guarantees co-residency
// (148 SMs x 6 = 888 >= 768), required for the spin barrier.
// ---------------------------------------------------------------------------
__global__ __launch_bounds__(256, 6) void fused_kernel(
        const float* __restrict__ x,
        const float* __restrict__ w1,
        const float* __restrict__ gamma,
        const float* __restrict__ beta,
        const float* __restrict__ rmean,
        const float* __restrict__ rvar,
        const float* __restrict__ w2,
        const float* __restrict__ b2,
        const float* __restrict__ bias,
        float* __restrict__ out) {
    const int bc  = blockIdx.x;            // 0..767 (this block's plane)
    const int b   = bc / DIMC;
    const int c   = bc % DIMC;
    const int tid = threadIdx.x;
    const int lane = tid & 31;
    const int wrp  = tid >> 5;

    // ================= Phase 1: pool own plane (ascending rows) ============
    const float* base = x + (size_t)bc * HWSZ;
    {
        const float4* p = (const float4*)base;
        float s = 0.f;
        for (int i = tid; i < HWSZ / 4; i += 256) {
            float4 v = p[i];
            s += (v.x + v.y) + (v.z + v.w);
        }
        #pragma unroll
        for (int o = 16; o > 0; o >>= 1) s += __shfl_down_sync(0xffffffffu, s, o);
        __shared__ float sm[8];
        if (lane == 0) sm[wrp] = s;
        __syncthreads();
        if (tid == 0) {
            float t = sm[0]+sm[1]+sm[2]+sm[3]+sm[4]+sm[5]+sm[6]+sm[7];
            g_pooled[bc] = t * (1.0f / (float)HWSZ);
        }
    }

    // ================= Grid barrier (ticket-based, replay-safe) ============
    if (tid == 0) {
        __threadfence();                               // publish g_pooled[bc]
        unsigned int ticket = atomicAdd(&g_sync, 1u);
        unsigned int target = ticket - (ticket % NPLANES) + NPLANES;
        volatile unsigned int* vs = &g_sync;
        while (*vs < target) __nanosleep(64);
    }
    __syncthreads();
    __threadfence();                                   // acquire

    // ================= Phase 2: weight-gen for this plane ==================
    __shared__ float t48[RJ];
    __shared__ float wts[4];
    if (tid < RJ) {
        const float* pw = w1 + tid * DIMC;
        const float* pp = g_pooled + b * DIMC;
        float acc = 0.f;
        #pragma unroll 8
        for (int cc = 0; cc < DIMC; cc++)
            acc = fmaf(__ldcg(pp + cc), pw[cc], acc);
        acc = gamma[tid] * (acc - rmean[tid]) * rsqrtf(rvar[tid] + EPSV) + beta[tid];
        t48[tid] = fmaxf(acc, 0.f);
    }
    __syncthreads();
    if (tid < 4) {                                     // mask 'A' taps 0..3
        const int o = c * 9 + tid;
        const float* pw2 = w2 + (size_t)o * RJ;
        float acc = b2[o];
        #pragma unroll
        for (int j = 0; j < RJ; j++) acc = fmaf(t48[j], pw2[j], acc);
        wts[tid] = acc;
    }
    __syncthreads();
    const float w0 = wts[0], w1t = wts[1], w2t = wts[2], w3 = wts[3];
    const float bs = bias[c];

    // ================= Phase 3: conv own plane, tiles DESCENDING ===========
    // Tail rows of this plane are this block's freshest L2 lines from pool.
    //   out(y,x) = w0*in(y-1,x-1)+w1*in(y-1,x)+w2*in(y-1,x+1)+w3*in(y,x-1)+bias
    float* outp = out + (size_t)bc * HWSZ;
    const int x0 = lane << 3;                          // 8 floats per thread
    for (int tile = ROWTILES - 1; tile >= 0; tile--) {
        const int y = tile * 8 + wrp;
        const float* rowc = base + y * WW;
        const float* rowm = rowc - WW;                 // valid only when y>0

        const float4 b0 = __ldcs((const float4*)(rowc + x0));
        const float4 b1 = __ldcs((const float4*)(rowc + x0 + 4));

        float4 a0, a1;
        if (y > 0) {                                   // warp-uniform
            a0 = __ldcs((const float4*)(rowm + x0));
            a1 = __ldcs((const float4*)(rowm + x0 + 4));
        } else {
            a0 = make_float4(0.f, 0.f, 0.f, 0.f); a1 = a0;
        }

        float am1 = __shfl_up_sync(0xffffffffu, a1.w, 1);
        float bm1 = __shfl_up_sync(0xffffffffu, b1.w, 1);
        float ap8 = __shfl_down_sync(0xffffffffu, a0.x, 1);
        if (lane == 0)  { am1 = 0.f; bm1 = 0.f; }
        if (lane == 31) { ap8 = 0.f; }

        const float A[10] = {am1, a0.x, a0.y, a0.z, a0.w,
                             a1.x, a1.y, a1.z, a1.w, ap8};
        const float Bv[8] = {bm1, b0.x, b0.y, b0.z, b0.w, b1.x, b1.y, b1.z};

        float o[8];
        #pragma unroll
        for (int i = 0; i < 8; i++)
            o[i] = fmaf(w0, A[i], fmaf(w1t, A[i+1],
                   fmaf(w2t, A[i+2], fmaf(w3, Bv[i], bs))));

        float* po = outp + y * WW + x0;
        __stcs((float4*)po,     make_float4(o[0], o[1], o[2], o[3]));
        __stcs((float4*)po + 1, make_float4(o[4], o[5], o[6], o[7]));
    }
}

// ---------------------------------------------------------------------------
extern "C" void kernel_launch(void* const* d_in, const int* in_sizes, int n_in,
                              void* d_out, int out_size) {
    const float* x     = (const float*)d_in[0];
    const float* w1    = (const float*)d_in[1];
    const float* gamma = (const float*)d_in[2];
    const float* beta  = (const float*)d_in[3];
    const float* rmean = (const float*)d_in[4];
    const float* rvar  = (const float*)d_in[5];
    const float* w2    = (const float*)d_in[6];
    const float* b2    = (const float*)d_in[7];
    const float* bias  = (const float*)d_in[8];
    float* out = (float*)d_out;

    fused_kernel<<<NPLANES, 256>>>(x, w1, gamma, beta, rmean, rvar,
                                   w2, b2, bias, out);
}